// round 9
// baseline (speedup 1.0000x reference)
#include <cuda_runtime.h>
#include <cstdint>

static constexpr int D      = 128;
static constexpr int K      = 8;
static constexpr int WARPS  = 4;      // per block (128 threads)
static constexpr int ITERS  = 8;      // iterations per warp
static constexpr int PPI    = 2;      // pairs per iteration
static constexpr int STAGES = 4;      // cp.async ring depth
static constexpr int STAGE_FLOATS = PPI * 2 * D;      // 512 floats = 2048 B
static constexpr int STAGE_BYTES  = STAGE_FLOATS * 4; // 2048
static constexpr int ROW_BYTES    = D * 4;            // 512

__global__ void spl_zero_kernel(float* out) { *out = 0.0f; }

__device__ __forceinline__ void cpa16(uint32_t dst, const float* src) {
    asm volatile("cp.async.cg.shared.global [%0], [%1], 16;\n" :: "r"(dst), "l"(src));
}
__device__ __forceinline__ void cpa_commit() {
    asm volatile("cp.async.commit_group;\n" ::: "memory");
}
__device__ __forceinline__ void cpa_wait2() {
    asm volatile("cp.async.wait_group 2;\n" ::: "memory");
}

__global__ __launch_bounds__(WARPS * 32) void spl_loss_kernel(
    const float* __restrict__ emb,
    const int*   __restrict__ pair_ids,
    const int*   __restrict__ dims,
    float*       __restrict__ out,
    int n_pairs, float inv_p)
{
    const unsigned FULL = 0xFFFFFFFFu;
    const int lane = threadIdx.x & 31;
    const int wid  = threadIdx.x >> 5;

    __shared__ float rows[WARPS][STAGES * STAGE_FLOATS];   // 4 x 8KB = 32KB
    __shared__ float warp_sums[WARPS];

    const int  warp_global = blockIdx.x * WARPS + wid;
    const int  base        = warp_global * (PPI * ITERS);
    float*     mybuf       = rows[wid];
    uint32_t   sb = (uint32_t)__cvta_generic_to_shared(mybuf) + lane * 16;

    const int  id4_max = (n_pairs >> 1) - 1;
    const long dim_max = (long)n_pairs * K - 1;

    float c = 0.0f;
    if (base < n_pairs) {
        auto load_ids = [&](int i) -> int4 {
            int idx = warp_global * ITERS + i;
            if (idx > id4_max) idx = id4_max;
            return __ldg((const int4*)pair_ids + idx);
        };
        auto load_dim = [&](int i) -> int {
            long idx = (long)(base + PPI * i) * K + lane;   // lanes 0..15 used
            if (idx > dim_max) idx = dim_max;
            return __ldg(dims + idx);
        };
        auto valid = [&](int i, int sub) { return base + PPI * i + sub < n_pairs; };
        auto issue_stage = [&](int s, int4 pr, bool v0, bool v1) {
            uint32_t dst = sb + (uint32_t)s * STAGE_BYTES;
            if (v0) {
                cpa16(dst,                 emb + (size_t)pr.x * D + lane * 4);
                cpa16(dst + ROW_BYTES,     emb + (size_t)pr.y * D + lane * 4);
            }
            if (v1) {
                cpa16(dst + 2 * ROW_BYTES, emb + (size_t)pr.z * D + lane * 4);
                cpa16(dst + 3 * ROW_BYTES, emb + (size_t)pr.w * D + lane * 4);
            }
        };

        // ---- prologue: prefetch all indices, launch 3 stages ----
        int4 ids_q[STAGES];
        int  dim_q[ITERS];
        #pragma unroll
        for (int i = 0; i < STAGES; i++) ids_q[i] = load_ids(i);
        #pragma unroll
        for (int i = 0; i < ITERS; i++)  dim_q[i] = load_dim(i);

        #pragma unroll
        for (int i = 0; i < 3; i++) {
            issue_stage(i, ids_q[i], valid(i, 0), valid(i, 1));
            cpa_commit();
        }
        // slots 0..2 free again: preload ids for iters 4..6
        #pragma unroll
        for (int i = 4; i < ITERS - 1 && i < 4 + 3; i++)
            ids_q[i & (STAGES - 1)] = load_ids(i);

        #pragma unroll
        for (int i = 0; i < ITERS; i++) {
            // wait for stage i (<=2 younger groups pending), make writes warp-visible
            cpa_wait2();
            __syncwarp();

            const float* buf = mybuf + (i & (STAGES - 1)) * STAGE_FLOATS;
            const bool v0 = valid(i, 0);
            const bool v1 = valid(i, 1);

            // polarity gathers from smem rows; lanes 0-7 pair0, 8-15 pair1
            const int  mydim = dim_q[i];
            const bool pol   = (lane < 8) ? v0 : (lane < 16 && v1);
            float g1 = 0.0f, g2 = 0.0f;
            if (pol) {
                int rs = (lane >> 3) * 256;
                g1 = buf[rs + mydim];
                g2 = buf[rs + 128 + mydim];
            }

            // duplicate-dim detection: one MATCH + one ballot
            int key = pol ? (mydim + ((lane & 8) << 5)) : (1024 + lane);
            unsigned mm = __match_any_sync(FULL, key);
            bool leader = ((mm & ((1u << lane) - 1u)) == 0u);
            unsigned lb = __ballot_sync(FULL, leader && pol);
            int distinct0 = __popc(lb & 0x00FFu);
            int distinct1 = __popc(lb & 0xFF00u);
            float invk0 = v0 ? __fdividef(0.5f, (float)(D - distinct0)) : 0.0f;
            float invk1 = v1 ? __fdividef(0.5f, (float)(D - distinct1)) : 0.0f;

            // full-row diff^2 totals (each lane: its 4 elements of each pair)
            float4 A0 = ((const float4*)buf)[lane];
            float4 B0 = ((const float4*)(buf + 128))[lane];
            float4 A1 = make_float4(0.f, 0.f, 0.f, 0.f), B1 = A1;
            if (v1) {
                A1 = ((const float4*)(buf + 256))[lane];
                B1 = ((const float4*)(buf + 384))[lane];
            }
            float dx0 = A0.x - B0.x, dy0 = A0.y - B0.y, dz0 = A0.z - B0.z, dw0 = A0.w - B0.w;
            float dx1 = A1.x - B1.x, dy1 = A1.y - B1.y, dz1 = A1.z - B1.z, dw1 = A1.w - B1.w;
            float t0 = fmaf(dx0, dx0, fmaf(dy0, dy0, fmaf(dz0, dz0, dw0 * dw0)));
            float t1 = fmaf(dx1, dx1, fmaf(dy1, dy1, fmaf(dz1, dz1, dw1 * dw1)));
            c = fmaf(t0, invk0, fmaf(t1, invk1, c));

            if (pol) {
                // polarity (duplicates counted; sign_prod==0 iff either value is +-0)
                float s   = fabsf(g1) + fabsf(g2);
                bool zero = (g1 == 0.0f) || (g2 == 0.0f);
                bool opp  = ((__float_as_int(g1) ^ __float_as_int(g2)) < 0);
                c += zero ? 0.1f : (opp ? -0.5f * s : s);
                // remove selected-dim diff^2 (distinct dims only -> leader lanes)
                if (leader) {
                    float dd = g1 - g2;
                    c = fmaf(-dd * dd, (lane < 8) ? invk0 : invk1, c);
                }
            }

            // issue stage i+3 (slot reuse distance 1 iter: waited+synced above)
            if (i + 3 < ITERS) {
                int slot = (i + 3) & (STAGES - 1);
                issue_stage(slot, ids_q[slot], valid(i + 3, 0), valid(i + 3, 1));
            }
            cpa_commit();                      // uniform group accounting
            if (i + 7 < ITERS)
                ids_q[(i + 7) & (STAGES - 1)] = load_ids(i + 7);
        }
    }

    // ---- warp butterfly + block reduce + one atomic per block ----
    #pragma unroll
    for (int off = 16; off > 0; off >>= 1)
        c += __shfl_xor_sync(FULL, c, off);
    if (lane == 0) warp_sums[wid] = c;
    __syncthreads();
    if (threadIdx.x == 0) {
        float s = 0.0f;
        #pragma unroll
        for (int v = 0; v < WARPS; v++) s += warp_sums[v];
        atomicAdd(out, s * inv_p);
    }
}

extern "C" void kernel_launch(void* const* d_in, const int* in_sizes, int n_in,
                              void* d_out, int out_size)
{
    const float* emb      = (const float*)d_in[0];  // (VOCAB, 128) f32
    const int*   pair_ids = (const int*)  d_in[1];  // (P, 2) i32
    const int*   dims     = (const int*)  d_in[2];  // (P, 8) i32
    float*       out      = (float*)d_out;          // scalar f32

    int n_pairs = in_sizes[1] / 2;
    spl_zero_kernel<<<1, 1>>>(out);

    int pairs_per_warp = PPI * ITERS;                        // 16
    int warps_needed   = (n_pairs + pairs_per_warp - 1) / pairs_per_warp;
    int blocks         = (warps_needed + WARPS - 1) / WARPS;
    spl_loss_kernel<<<blocks, WARPS * 32>>>(emb, pair_ids, dims, out,
                                            n_pairs, 1.0f / (float)n_pairs);
}

// round 10
// speedup vs baseline: 1.1536x; 1.1536x over previous
#include <cuda_runtime.h>
#include <cstdint>

static constexpr int D   = 128;
static constexpr int K   = 8;
static constexpr int PPW = 3;       // pairs per warp

__global__ void spl_zero_kernel(float* out) { *out = 0.0f; }

// float4 load with L2 evict_last policy (keeps the embedding table L2-resident).
__device__ __forceinline__ float4 ldg_el4(const float4* p, uint64_t pol) {
    float4 v;
    asm volatile("ld.global.nc.L2::cache_hint.v4.f32 {%0,%1,%2,%3}, [%4], %5;"
                 : "=f"(v.x), "=f"(v.y), "=f"(v.z), "=f"(v.w)
                 : "l"(p), "l"(pol));
    return v;
}
__device__ __forceinline__ float ldg_el1(const float* p, uint64_t pol) {
    float v;
    asm volatile("ld.global.nc.L2::cache_hint.f32 %0, [%1], %2;"
                 : "=f"(v) : "l"(p), "l"(pol));
    return v;
}

__global__ __launch_bounds__(256) void spl_loss_kernel(
    const float* __restrict__ emb,
    const int*   __restrict__ pair_ids,
    const int*   __restrict__ dims,
    float*       __restrict__ out,
    int n_pairs, float inv_p)
{
    const unsigned FULL = 0xFFFFFFFFu;
    const int lane = threadIdx.x & 31;
    const int wid  = threadIdx.x >> 5;          // 8 warps per block
    const int p0   = (blockIdx.x * 8 + wid) * PPW;

    __shared__ float warp_sums[8];

    float c = 0.0f;
    if (p0 < n_pairs) {
        uint64_t pol64;
        asm volatile("createpolicy.fractional.L2::evict_last.b64 %0, 1.0;" : "=l"(pol64));

        const bool v1 = (p0 + 1) < n_pairs;
        const bool v2 = (p0 + 2) < n_pairs;
        const int  pmax = n_pairs - 1;

        // Per-pair id loads (uniform per warp, clamped for tail pairs).
        int2 i0 = __ldg((const int2*)pair_ids + p0);
        int2 i1 = __ldg((const int2*)pair_ids + (v1 ? p0 + 1 : pmax));
        int2 i2 = __ldg((const int2*)pair_ids + (v2 ? p0 + 2 : pmax));

        const float* r0a = emb + (size_t)i0.x * D;
        const float* r0b = emb + (size_t)i0.y * D;
        const float* r1a = emb + (size_t)i1.x * D;
        const float* r1b = emb + (size_t)i1.y * D;
        const float* r2a = emb + (size_t)i2.x * D;
        const float* r2b = emb + (size_t)i2.y * D;

        // 6 independent coalesced row reads, all in flight together.
        float4 A0 = ldg_el4((const float4*)r0a + lane, pol64);
        float4 B0 = ldg_el4((const float4*)r0b + lane, pol64);
        float4 A1 = ldg_el4((const float4*)r1a + lane, pol64);
        float4 B1 = ldg_el4((const float4*)r1b + lane, pol64);
        float4 A2 = ldg_el4((const float4*)r2a + lane, pol64);
        float4 B2 = ldg_el4((const float4*)r2b + lane, pol64);

        // Dims: lanes 0..23 cover 3 pairs x 8 dims (contiguous ints).
        const int g = lane >> 3;                       // pair group 0..3
        const bool gvalid = (g == 0) || (g == 1 && v1) || (g == 2 && v2);
        const bool pol = (lane < 24) && gvalid;
        int mydim = 0;
        if (lane < 24) {
            long idx = (long)p0 * K + lane;
            long dmax = (long)n_pairs * K - 1;
            mydim = __ldg(dims + (idx > dmax ? dmax : idx));
        }

        // Polarity gathers (lines already L1/L2-resident from the row loads).
        float g1 = 0.0f, g2 = 0.0f;
        if (pol) {
            const float* ra = (g == 0) ? r0a : (g == 1) ? r1a : r2a;
            const float* rb = (g == 0) ? r0b : (g == 1) ? r1b : r2b;
            g1 = ldg_el1(ra + mydim, pol64);
            g2 = ldg_el1(rb + mydim, pol64);
        }

        // Duplicate-dim detection: one MATCH + one ballot.
        int key = pol ? (mydim + (g << 8)) : (0x8000 + lane);
        unsigned mm = __match_any_sync(FULL, key);
        bool leader = ((mm & ((1u << lane) - 1u)) == 0u);
        unsigned lb = __ballot_sync(FULL, leader && pol);
        int d0 = __popc(lb & 0x0000FFu);
        int d1 = __popc(lb & 0x00FF00u);
        int d2 = __popc(lb & 0xFF0000u);
        float invk0 = __fdividef(0.5f, (float)(D - d0));
        float invk1 = v1 ? __fdividef(0.5f, (float)(D - d1)) : 0.0f;
        float invk2 = v2 ? __fdividef(0.5f, (float)(D - d2)) : 0.0f;

        // Full-row diff^2 totals (each lane: 4 elements of each pair).
        float dx, dy, dz, dw;
        dx = A0.x - B0.x; dy = A0.y - B0.y; dz = A0.z - B0.z; dw = A0.w - B0.w;
        float t0 = fmaf(dx, dx, fmaf(dy, dy, fmaf(dz, dz, dw * dw)));
        dx = A1.x - B1.x; dy = A1.y - B1.y; dz = A1.z - B1.z; dw = A1.w - B1.w;
        float t1 = fmaf(dx, dx, fmaf(dy, dy, fmaf(dz, dz, dw * dw)));
        dx = A2.x - B2.x; dy = A2.y - B2.y; dz = A2.z - B2.z; dw = A2.w - B2.w;
        float t2 = fmaf(dx, dx, fmaf(dy, dy, fmaf(dz, dz, dw * dw)));
        c = fmaf(t0, invk0, fmaf(t1, invk1, fmaf(t2, invk2, c)));

        if (pol) {
            // polarity (duplicates counted; sign_prod==0 iff either value is +-0)
            float s   = fabsf(g1) + fabsf(g2);
            bool zero = (g1 == 0.0f) || (g2 == 0.0f);
            bool opp  = ((__float_as_int(g1) ^ __float_as_int(g2)) < 0);
            c += zero ? 0.1f : (opp ? -0.5f * s : s);
            // subtract selected-dim diff^2 (distinct dims only -> leader lanes)
            if (leader) {
                float dd = g1 - g2;
                float ik = (g == 0) ? invk0 : (g == 1) ? invk1 : invk2;
                c = fmaf(-dd * dd, ik, c);
            }
        }
    }

    // ---- warp butterfly + block reduce + one atomic per block ----
    #pragma unroll
    for (int off = 16; off > 0; off >>= 1)
        c += __shfl_xor_sync(FULL, c, off);
    if (lane == 0) warp_sums[wid] = c;
    __syncthreads();
    if (threadIdx.x == 0) {
        float s = 0.0f;
        #pragma unroll
        for (int v = 0; v < 8; v++) s += warp_sums[v];
        atomicAdd(out, s * inv_p);
    }
}

extern "C" void kernel_launch(void* const* d_in, const int* in_sizes, int n_in,
                              void* d_out, int out_size)
{
    const float* emb      = (const float*)d_in[0];  // (VOCAB, 128) f32
    const int*   pair_ids = (const int*)  d_in[1];  // (P, 2) i32
    const int*   dims     = (const int*)  d_in[2];  // (P, 8) i32
    float*       out      = (float*)d_out;          // scalar f32

    int n_pairs = in_sizes[1] / 2;
    spl_zero_kernel<<<1, 1>>>(out);

    int pairs_per_block = 8 * PPW;                  // 24
    int blocks = (n_pairs + pairs_per_block - 1) / pairs_per_block;
    spl_loss_kernel<<<blocks, 256>>>(emb, pair_ids, dims, out,
                                     n_pairs, 1.0f / (float)n_pairs);
}